// round 16
// baseline (speedup 1.0000x reference)
#include <cuda_runtime.h>
#include <cuda_bf16.h>
#include <cstdint>

#define NN 1024
#define SS 144
#define RR 96
#define KK 128
#define DD 768
#define AA 48
#define RK (RR*KK)         // 12288
#define SPLITK 3
#define KSPLIT (RK/SPLITK) // 4096

#define KCH 32                 // K elems per logical stage
#define PLANE_B 16384          // 128 rows x 128B (two 64B half-chunks per row)
#define PHYS_B  (4*PLANE_B)    // Ahi Alo Bhi Blo (one physical buffer = 2 stages)
#define SM_TILES 2048
#define SMEMSZ (SM_TILES + 2*PHYS_B)   // 133120
#define NSTG 4
#define SM_LAM 1024
#define SM_LMB 1536
#define NTHREADS 384           // 8 consumer warps + 4 producer warps

// Named barriers (id 0 reserved for __syncthreads):
//   full[s]  = id 1+s : producers(128) bar.arrive, consumers(256) bar.sync, count 384
//   empty[s] = id 5+s : consumers(256) bar.arrive, producers(128) bar.sync, count 384
#define BAR_SYNC(id)   asm volatile("bar.sync %0, %1;"   :: "r"(id), "r"(NTHREADS) : "memory")
#define BAR_ARRIVE(id) asm volatile("bar.arrive %0, %1;" :: "r"(id), "r"(NTHREADS) : "memory")

// ---- scratch (device globals; only referenced from device code) ----
__device__ unsigned g_chl[(size_t)NN * RK];          // coeffs packed bf16 hi/lo
__device__ unsigned g_ivt[(size_t)DD * RK];          // invb^T packed bf16 hi/lo
__device__ float    g_part[(size_t)SPLITK * NN * DD];// split-K partials
__device__ float    g_lamk[RK];
__device__ float    g_lmb[RK];
__device__ int      g_ridx[RR];
__device__ int      g_aidx[AA];

// ---- helpers ----
__device__ __forceinline__ uint32_t smem_u32(const void* p) {
    uint32_t a; asm("{ .reg .u64 t; cvta.to.shared.u64 t, %1; cvt.u32.u64 %0, t; }" : "=r"(a) : "l"(p));
    return a;
}
#define SWZ(o) ((o) ^ (((o) >> 3) & 0x70))

__device__ __forceinline__ void ldsm4(uint32_t* r, uint32_t addr) {
    asm volatile("ldmatrix.sync.aligned.m8n8.x4.shared.b16 {%0,%1,%2,%3}, [%4];"
        : "=r"(r[0]), "=r"(r[1]), "=r"(r[2]), "=r"(r[3]) : "r"(addr));
}
__device__ __forceinline__ void mma16816(float* c, const uint32_t* a, uint32_t b0, uint32_t b1) {
    asm volatile("mma.sync.aligned.m16n8k16.row.col.f32.bf16.bf16.f32 "
        "{%0,%1,%2,%3}, {%4,%5,%6,%7}, {%8,%9}, {%0,%1,%2,%3};"
        : "+f"(c[0]), "+f"(c[1]), "+f"(c[2]), "+f"(c[3])
        : "r"(a[0]), "r"(a[1]), "r"(a[2]), "r"(a[3]), "r"(b0), "r"(b1));
}

// fp32 pair -> packed bf16 hi + bf16 lo
__device__ __forceinline__ void split2(float x, float y, unsigned& h, unsigned& l) {
    unsigned hp; asm("cvt.rn.bf16x2.f32 %0, %1, %2;" : "=r"(hp) : "f"(y), "f"(x));
    float hx = __uint_as_float(hp << 16);
    float hy = __uint_as_float(hp & 0xFFFF0000u);
    asm("cvt.rn.bf16x2.f32 %0, %1, %2;" : "=r"(l) : "f"(y - hy), "f"(x - hx));
    h = hp;
}
__device__ __forceinline__ void split8(float4 a, float4 b, uint4& h, uint4& l) {
    split2(a.x, a.y, h.x, l.x); split2(a.z, a.w, h.y, l.y);
    split2(b.x, b.y, h.z, l.z); split2(b.z, b.w, h.w, l.w);
}
__device__ __forceinline__ unsigned packhl(float v) {
    __nv_bfloat16 h = __float2bfloat16(v);
    float hf = __bfloat162float(h);
    __nv_bfloat16 lo = __float2bfloat16(v - hf);
    return ((unsigned)__bfloat16_as_ushort(h) << 16) | (unsigned)__bfloat16_as_ushort(lo);
}
__device__ __forceinline__ void unpack2(unsigned w0, unsigned w1, unsigned& h, unsigned& l) {
    h = (w1 & 0xFFFF0000u) | (w0 >> 16);
    l = (w1 << 16) | (w0 & 0xFFFFu);
}
__device__ __forceinline__ void unpack8(uint4 w0, uint4 w1, uint4& h, uint4& l) {
    unpack2(w0.x, w0.y, h.x, l.x); unpack2(w0.z, w0.w, h.y, l.y);
    unpack2(w1.x, w1.y, h.z, l.z); unpack2(w1.z, w1.w, h.w, l.w);
}

// ---------------------------------------------------------------------------
// prep1 / prep2 / tr_invb / ablate : verified in earlier rounds
// ---------------------------------------------------------------------------
__global__ void prep1_k(const int* __restrict__ rraw, const int* __restrict__ araw,
                        const float* __restrict__ lambdas, const int* __restrict__ blen) {
    __shared__ int soff[RR];
    int t = threadIdx.x;
    bool r64 = (rraw[1] == 0);
    bool a64 = (araw[1] == 0);
    if (t < RR) g_ridx[t] = r64 ? rraw[2 * t] : rraw[t];
    if (t < AA) g_aidx[t] = a64 ? araw[2 * t] : araw[t];
    if (t == 0) {
        int acc = 0;
        for (int r = 0; r < RR; r++) { soff[r] = acc; acc += blen[r]; }
    }
    __syncthreads();
    for (int i = t; i < RK; i += 128) {
        int r = i >> 7, k = i & 127;
        g_lamk[i] = (k < blen[r]) ? lambdas[soff[r] + k] : 0.0f;
    }
}

__global__ void prep2_k(const float* __restrict__ bases, const float* __restrict__ means) {
    int gw = (blockIdx.x * blockDim.x + threadIdx.x) >> 5;
    int lane = threadIdx.x & 31;
    if (gw >= RK) return;
    int r = gw >> 7;
    const float4* b4 = (const float4*)(bases + (size_t)gw * DD);
    const float4* m4 = (const float4*)(means + (size_t)r * DD);
    float s = 0.f;
    #pragma unroll 3
    for (int j = lane; j < DD / 4; j += 32) {
        float4 bb = b4[j], mm = m4[j];
        s += bb.x * mm.x + bb.y * mm.y + bb.z * mm.z + bb.w * mm.w;
    }
    #pragma unroll
    for (int o = 16; o; o >>= 1) s += __shfl_xor_sync(0xffffffffu, s, o);
    if (lane == 0) g_lmb[gw] = g_lamk[gw] * s;
}

__global__ void tr_invb_k(const float* __restrict__ invb) {
    __shared__ float t[32][33];
    int rk0 = blockIdx.x << 5, d0 = blockIdx.y << 5;
    int r = threadIdx.x >> 3, c4 = (threadIdx.x & 7) << 2;
    float4 v = *(const float4*)(invb + (size_t)(rk0 + r) * DD + d0 + c4);
    t[r][c4] = v.x; t[r][c4 + 1] = v.y; t[r][c4 + 2] = v.z; t[r][c4 + 3] = v.w;
    __syncthreads();
    uint4 o;
    o.x = packhl(t[c4 + 0][r]); o.y = packhl(t[c4 + 1][r]);
    o.z = packhl(t[c4 + 2][r]); o.w = packhl(t[c4 + 3][r]);
    *(uint4*)(g_ivt + (size_t)(d0 + r) * RK + rk0 + c4) = o;
}

__global__ void ablate_k(const float* __restrict__ x, float* __restrict__ out) {
    __shared__ int sa[AA];
    if (threadIdx.x < AA) sa[threadIdx.x] = g_aidx[threadIdx.x];
    __syncthreads();
    int i = blockIdx.x * 256 + threadIdx.x;
    int n = i / (DD / 4), c = i % (DD / 4);
    const float4* x4 = (const float4*)x;
    float4 s = make_float4(0.f, 0.f, 0.f, 0.f);
    int base = n * SS;
    #pragma unroll 4
    for (int a = 0; a < AA; a++) {
        float4 v = x4[(size_t)(base + sa[a]) * (DD / 4) + c];
        s.x += v.x; s.y += v.y; s.z += v.z; s.w += v.w;
    }
    ((float4*)out)[i] = s;
}

// ---------------------------------------------------------------------------
// consumer MMA over one K32 logical stage (8 warps, 2x4 grid, 64x32/warp).
// ---------------------------------------------------------------------------
__device__ __forceinline__ void mma_chunk(uint32_t buf_addr, uint32_t h64,
                                          int wm, int wn, int lane, float acc[4][4][4]) {
    const int lr = lane & 15, lc8 = lane >> 4;
    #pragma unroll
    for (int ks = 0; ks < 2; ks++) {
        const uint32_t kb = h64 + (uint32_t)(ks * 32 + lc8 * 16);
        uint32_t ah[4][4], al[4][4];
        #pragma unroll
        for (int mf = 0; mf < 4; mf++) {
            uint32_t off = SWZ((uint32_t)((wm * 64 + mf * 16 + lr) * 128) + kb);
            ldsm4(ah[mf], buf_addr + off);
            ldsm4(al[mf], buf_addr + PLANE_B + off);
        }
        uint32_t bh[2][4], bl[2][4];
        #pragma unroll
        for (int ng = 0; ng < 2; ng++) {
            uint32_t off = SWZ((uint32_t)((wn * 32 + ng * 16 + lr) * 128) + kb);
            ldsm4(bh[ng], buf_addr + 2 * PLANE_B + off);
            ldsm4(bl[ng], buf_addr + 3 * PLANE_B + off);
        }
        #pragma unroll
        for (int mf = 0; mf < 4; mf++) {
            #pragma unroll
            for (int j = 0; j < 4; j++) {
                const int ng = j >> 1, s = j & 1;
                mma16816(acc[mf][j], ah[mf], bh[ng][s], bh[ng][s + 2]);
                mma16816(acc[mf][j], ah[mf], bl[ng][s], bl[ng][s + 2]);
                mma16816(acc[mf][j], al[mf], bh[ng][s], bh[ng][s + 2]);
            }
        }
    }
}

// ---------------------------------------------------------------------------
// gemm1_nb: warp-specialized via named barriers. 8 consumer + 4 producer warps.
// C(128x128) = Xr @ Br^T, epilogue lam*C - lmb -> packed g_chl.
// ---------------------------------------------------------------------------
__global__ __launch_bounds__(NTHREADS, 1)
void gemm1_nb(const float* __restrict__ x, const float* __restrict__ bases) {
    extern __shared__ char sm[];
    const uint32_t sb = smem_u32(sm);
    const int tid = threadIdx.x, wid = tid >> 5, lane = tid & 31;
    const int r = blockIdx.y, n0 = blockIdx.x << 7;
    const int NCH = DD / KCH;  // 24

    if (tid < KK) {
        ((float*)(sm + SM_LAM))[tid] = g_lamk[(r << 7) + tid];
        ((float*)(sm + SM_LMB))[tid] = g_lmb[(r << 7) + tid];
    }
    __syncthreads();

    if (wid < 8) {
        // ---- consumers ----
        const int wm = wid & 1, wn = wid >> 1;
        float acc[4][4][4];
        #pragma unroll
        for (int a = 0; a < 4; a++)
            #pragma unroll
            for (int b = 0; b < 4; b++)
                #pragma unroll
                for (int c = 0; c < 4; c++) acc[a][b][c] = 0.f;
        for (int c = 0; c < NCH; c++) {
            const int s = c & (NSTG - 1);
            BAR_SYNC(1 + s);                      // wait full[s]
            mma_chunk(sb + SM_TILES + (s >> 1) * PHYS_B, (uint32_t)((s & 1) * 64),
                      wm, wn, lane, acc);
            BAR_ARRIVE(5 + s);                    // signal empty[s]
        }
        // epilogue
        const float* slam = (const float*)(sm + SM_LAM);
        const float* slmb = (const float*)(sm + SM_LMB);
        #pragma unroll
        for (int mf = 0; mf < 4; mf++) {
            const int grow = n0 + wm * 64 + mf * 16 + (lane >> 2);
            #pragma unroll
            for (int j = 0; j < 4; j++) {
                const int col = wn * 32 + j * 8 + 2 * (lane & 3);
                uint2 p;
                p.x = packhl(slam[col] * acc[mf][j][0] - slmb[col]);
                p.y = packhl(slam[col + 1] * acc[mf][j][1] - slmb[col + 1]);
                *(uint2*)(g_chl + (size_t)grow * RK + (r << 7) + col) = p;
                p.x = packhl(slam[col] * acc[mf][j][2] - slmb[col]);
                p.y = packhl(slam[col + 1] * acc[mf][j][3] - slmb[col + 1]);
                *(uint2*)(g_chl + (size_t)(grow + 8) * RK + (r << 7) + col) = p;
            }
        }
    } else {
        // ---- producers (4 warps = 128 threads; thread t owns row t) ----
        const int t = tid - 256;
        const float* Arow = x + ((size_t)(n0 + t) * SS + g_ridx[r]) * DD;
        const float* Brow = bases + ((size_t)r * KK + t) * DD;
        for (int c = 0; c < NCH; c++) {
            const int s = c & (NSTG - 1);
            if (c >= NSTG) BAR_SYNC(5 + s);       // wait empty[s] (skip first ring pass)
            char* buf = sm + SM_TILES + (s >> 1) * PHYS_B;
            const uint32_t h64 = (uint32_t)((s & 1) * 64);
            const int d0 = c * KCH;
            #pragma unroll
            for (int g = 0; g < 4; g++) {
                const uint32_t off = SWZ((uint32_t)(t * 128) + h64 + g * 16);
                float4 a0 = *(const float4*)(Arow + d0 + g * 8);
                float4 a1 = *(const float4*)(Arow + d0 + g * 8 + 4);
                uint4 h, l; split8(a0, a1, h, l);
                *(uint4*)(buf + off) = h;
                *(uint4*)(buf + PLANE_B + off) = l;
                float4 b0 = *(const float4*)(Brow + d0 + g * 8);
                float4 b1 = *(const float4*)(Brow + d0 + g * 8 + 4);
                split8(b0, b1, h, l);
                *(uint4*)(buf + 2 * PLANE_B + off) = h;
                *(uint4*)(buf + 3 * PLANE_B + off) = l;
            }
            BAR_ARRIVE(1 + s);                    // signal full[s]
        }
        #pragma unroll
        for (int s = 0; s < NSTG; s++) BAR_SYNC(5 + s);   // drain trailing empties
    }
}

// ---------------------------------------------------------------------------
// gemm2_nb: warp-specialized via named barriers.
// part[z] = coeffs[:,kz] @ invbT[d,kz]^T; A from g_chl, B from g_ivt (packed).
// ---------------------------------------------------------------------------
__global__ __launch_bounds__(NTHREADS, 1)
void gemm2_nb() {
    extern __shared__ char sm[];
    const uint32_t sb = smem_u32(sm);
    const int tid = threadIdx.x, wid = tid >> 5, lane = tid & 31;
    const int n0 = blockIdx.x << 7, d0 = blockIdx.y << 7, z = blockIdx.z;
    const int NCH = KSPLIT / KCH;  // 128

    if (wid < 8) {
        const int wm = wid & 1, wn = wid >> 1;
        float acc[4][4][4];
        #pragma unroll
        for (int a = 0; a < 4; a++)
            #pragma unroll
            for (int b = 0; b < 4; b++)
                #pragma unroll
                for (int c = 0; c < 4; c++) acc[a][b][c] = 0.f;
        for (int c = 0; c < NCH; c++) {
            const int s = c & (NSTG - 1);
            BAR_SYNC(1 + s);
            mma_chunk(sb + SM_TILES + (s >> 1) * PHYS_B, (uint32_t)((s & 1) * 64),
                      wm, wn, lane, acc);
            BAR_ARRIVE(5 + s);
        }
        float* P = g_part + (size_t)z * (NN * DD);
        #pragma unroll
        for (int mf = 0; mf < 4; mf++) {
            const int grow = n0 + wm * 64 + mf * 16 + (lane >> 2);
            #pragma unroll
            for (int j = 0; j < 4; j++) {
                const int col = d0 + wn * 32 + j * 8 + 2 * (lane & 3);
                *(float2*)(P + (size_t)grow * DD + col) = make_float2(acc[mf][j][0], acc[mf][j][1]);
                *(float2*)(P + (size_t)(grow + 8) * DD + col) = make_float2(acc[mf][j][2], acc[mf][j][3]);
            }
        }
    } else {
        const int t = tid - 256;
        const unsigned* Arow = g_chl + (size_t)(n0 + t) * RK + (size_t)z * KSPLIT;
        const unsigned* Brow = g_ivt + (size_t)(d0 + t) * RK + (size_t)z * KSPLIT;
        for (int c = 0; c < NCH; c++) {
            const int s = c & (NSTG - 1);
            if (c >= NSTG) BAR_SYNC(5 + s);
            char* buf = sm + SM_TILES + (s >> 1) * PHYS_B;
            const uint32_t h64 = (uint32_t)((s & 1) * 64);
            const int k0 = c * KCH;
            #pragma unroll
            for (int g = 0; g < 4; g++) {
                const uint32_t off = SWZ((uint32_t)(t * 128) + h64 + g * 16);
                uint4 w0 = *(const uint4*)(Arow + k0 + g * 8);
                uint4 w1 = *(const uint4*)(Arow + k0 + g * 8 + 4);
                uint4 h, l; unpack8(w0, w1, h, l);
                *(uint4*)(buf + off) = h;
                *(uint4*)(buf + PLANE_B + off) = l;
                w0 = *(const uint4*)(Brow + k0 + g * 8);
                w1 = *(const uint4*)(Brow + k0 + g * 8 + 4);
                unpack8(w0, w1, h, l);
                *(uint4*)(buf + 2 * PLANE_B + off) = h;
                *(uint4*)(buf + 3 * PLANE_B + off) = l;
            }
            BAR_ARRIVE(1 + s);
        }
        #pragma unroll
        for (int s = 0; s < NSTG; s++) BAR_SYNC(5 + s);
    }
}

// ---------------------------------------------------------------------------
// reduce_k: out += sum_z part[z]
// ---------------------------------------------------------------------------
__global__ void reduce_k(float* __restrict__ out) {
    int i = blockIdx.x * 256 + threadIdx.x;
    float4 s = ((const float4*)out)[i];
    const float4* p4 = (const float4*)g_part;
    #pragma unroll
    for (int zz = 0; zz < SPLITK; zz++) {
        float4 v = p4[(size_t)zz * (NN * DD / 4) + i];
        s.x += v.x; s.y += v.y; s.z += v.z; s.w += v.w;
    }
    ((float4*)out)[i] = s;
}

// ---------------------------------------------------------------------------
extern "C" void kernel_launch(void* const* d_in, const int* in_sizes, int n_in,
                              void* d_out, int out_size) {
    (void)in_sizes; (void)n_in; (void)out_size;
    const float* x       = (const float*)d_in[0];
    const float* lambdas = (const float*)d_in[1];
    const float* bases   = (const float*)d_in[2];
    const float* invb    = (const float*)d_in[3];
    const float* means   = (const float*)d_in[4];
    const int*   rraw    = (const int*)d_in[5];
    const int*   araw    = (const int*)d_in[6];
    const int*   blen    = (const int*)d_in[7];
    float* out = (float*)d_out;

    cudaFuncSetAttribute(gemm1_nb, cudaFuncAttributeMaxDynamicSharedMemorySize, SMEMSZ);
    cudaFuncSetAttribute(gemm2_nb, cudaFuncAttributeMaxDynamicSharedMemorySize, SMEMSZ);

    prep1_k<<<1, 128>>>(rraw, araw, lambdas, blen);
    prep2_k<<<1536, 256>>>(bases, means);
    tr_invb_k<<<dim3(RK / 32, DD / 32), 256>>>(invb);
    ablate_k<<<768, 256>>>(x, out);
    gemm1_nb<<<dim3(8, RR), NTHREADS, SMEMSZ>>>(x, bases);
    gemm2_nb<<<dim3(8, DD / 128, SPLITK), NTHREADS, SMEMSZ>>>();
    reduce_k<<<768, 256>>>(out);
}